// round 16
// baseline (speedup 1.0000x reference)
#include <cuda_runtime.h>
#include <cstdint>

#define B_ 16
#define T_ 8192
#define D_ 128
#define C_ 64
#define N_ 128

#define S1 132
#define SA 68

// scratch: wo / pre-chunk state ([i][j] layout), ksum / pre-chunk z
__device__ float g_wo[(size_t)B_ * N_ * D_ * D_];
__device__ float g_ks[(size_t)B_ * N_ * D_];

__device__ __forceinline__ float lam_from(const float* __restrict__ ld) {
    return 1.0f / (1.0f + __expf(-ld[0]));
}
// masked split: hi = top 19 bits (exactly tf32-representable), lo = exact residual
__device__ __forceinline__ void split2m(float x, uint32_t& h, uint32_t& l) {
    uint32_t hb = __float_as_uint(x) & 0xFFFFE000u;
    h = hb;
    l = __float_as_uint(x - __uint_as_float(hb));
}
__device__ __forceinline__ uint32_t smem_u32(const void* p) {
    uint32_t a;
    asm("{ .reg .u64 t; cvta.to.shared.u64 t, %1; cvt.u32.u64 %0, t; }" : "=r"(a) : "l"(p));
    return a;
}
__device__ __forceinline__ void cp16(uint32_t dst, const float* src) {
    asm volatile("cp.async.ca.shared.global [%0], [%1], 16;" :: "r"(dst), "l"(src) : "memory");
}
// D(16x8) += A(16x8,row) * B(8x8, B[k][n])
__device__ __forceinline__ void mma8(float* d, const uint32_t* a, const uint32_t* b) {
    asm volatile(
        "mma.sync.aligned.m16n8k8.row.col.f32.tf32.tf32.f32 "
        "{%0,%1,%2,%3},{%4,%5,%6,%7},{%8,%9},{%0,%1,%2,%3};"
        : "+f"(d[0]), "+f"(d[1]), "+f"(d[2]), "+f"(d[3])
        : "r"(a[0]), "r"(a[1]), "r"(a[2]), "r"(a[3]), "r"(b[0]), "r"(b[1]));
}
__device__ __forceinline__ void mma3(float* d, const uint32_t* ah, const uint32_t* al,
                                     const uint32_t* bh, const uint32_t* bl) {
    mma8(d, ah, bh);
    mma8(d, al, bh);
    mma8(d, ah, bl);
}

// ===========================================================================
// Kernel A: wo[i,j] = sum_c (cd_c k[c,i]) v[c,j].  (R15-proven, unchanged)
// ===========================================================================
#define A_RW 0
#define A_VV (A_RW + 64 * S1)
#define A_SC (A_VV + 64 * S1)
#define A_FLOATS (A_SC + 64)

__global__ __launch_bounds__(512) void wo_kernel(
    const float* __restrict__ k, const float* __restrict__ v,
    const float* __restrict__ ld)
{
    extern __shared__ float sm[];
    float* RW = sm + A_RW; float* VV = sm + A_VV; float* SC = sm + A_SC;
    const int tid = threadIdx.x;
    const int n = blockIdx.x, b = blockIdx.y;

    const float lam = lam_from(ld);
    if (tid < C_) SC[tid] = powf(lam, (float)(C_ - 1 - tid));
    __syncthreads();
    const size_t gbase = ((size_t)b * T_ + (size_t)n * C_) * D_;

#pragma unroll
    for (int u = 0; u < 4; u++) {
        int e = tid + u * 512;
        int c = e >> 5, d0 = (e & 31) * 4;
        float s = SC[c];
        float4 kk = *(const float4*)&k[gbase + (size_t)c * D_ + d0];
        *(float4*)&RW[c * S1 + d0] = make_float4(kk.x * s, kk.y * s, kk.z * s, kk.w * s);
        *(float4*)&VV[c * S1 + d0] = *(const float4*)&v[gbase + (size_t)c * D_ + d0];
    }
    __syncthreads();

    if (tid < D_) {
        float s = 0.f;
#pragma unroll 8
        for (int c = 0; c < C_; c++) s += RW[c * S1 + tid];
        g_ks[((size_t)b * N_ + n) * D_ + tid] = s;
    }

    const int lane = tid & 31, g = lane >> 2, t4 = lane & 3, wid = tid >> 5;
    const int wm = wid >> 2, wn = wid & 3;
    float acc[2][4][4];
#pragma unroll
    for (int mi = 0; mi < 2; mi++)
#pragma unroll
        for (int ni = 0; ni < 4; ni++)
#pragma unroll
            for (int e = 0; e < 4; e++) acc[mi][ni][e] = 0.f;

#pragma unroll
    for (int ks = 0; ks < 8; ks++) {
        int kb = ks * 8;
        uint32_t ah[2][4], al[2][4], bh[4][2], bl[4][2];
#pragma unroll
        for (int mi = 0; mi < 2; mi++) {
            int r0 = wm * 32 + mi * 16 + g;
            split2m(RW[(kb + t4) * S1 + r0],     ah[mi][0], al[mi][0]);
            split2m(RW[(kb + t4) * S1 + r0 + 8], ah[mi][1], al[mi][1]);
            split2m(RW[(kb + t4 + 4) * S1 + r0],     ah[mi][2], al[mi][2]);
            split2m(RW[(kb + t4 + 4) * S1 + r0 + 8], ah[mi][3], al[mi][3]);
        }
#pragma unroll
        for (int ni = 0; ni < 4; ni++) {
            int n0 = wn * 32 + ni * 8 + g;
            split2m(VV[(kb + t4) * S1 + n0],     bh[ni][0], bl[ni][0]);
            split2m(VV[(kb + t4 + 4) * S1 + n0], bh[ni][1], bl[ni][1]);
        }
#pragma unroll
        for (int mi = 0; mi < 2; mi++)
#pragma unroll
            for (int ni = 0; ni < 4; ni++)
                mma3(acc[mi][ni], ah[mi], al[mi], bh[ni], bl[ni]);
    }

    float* wb = g_wo + (((size_t)b * N_ + n) << 14);
#pragma unroll
    for (int mi = 0; mi < 2; mi++)
#pragma unroll
        for (int ni = 0; ni < 4; ni++) {
            int r0 = wm * 32 + mi * 16 + g, cc = wn * 32 + ni * 8 + 2 * t4;
            *(float2*)&wb[(size_t)r0 * D_ + cc]       = make_float2(acc[mi][ni][0], acc[mi][ni][1]);
            *(float2*)&wb[(size_t)(r0 + 8) * D_ + cc] = make_float2(acc[mi][ni][2], acc[mi][ni][3]);
        }
}

// ===========================================================================
// Kernel B: scans (proven).
// ===========================================================================
__global__ __launch_bounds__(256) void scan_state_kernel(
    const float* __restrict__ ld, float* __restrict__ out_state)
{
    const int gid = blockIdx.x * 256 + threadIdx.x;
    const int b = gid >> 12;
    const int e4 = gid & 4095;
    const float r = powf(lam_from(ld), (float)C_);
    float4 s = make_float4(0.f, 0.f, 0.f, 0.f);
    float4* p = (float4*)(g_wo + (((size_t)b * N_) << 14)) + e4;
    float4 w[4];
#pragma unroll
    for (int i = 0; i < 4; i++) w[i] = __ldcs(p + ((size_t)i << 12));
#pragma unroll 4
    for (int n = 0; n < N_; n++) {
        float4 wn = (n + 4 < N_) ? __ldcs(p + ((size_t)(n + 4) << 12))
                                 : make_float4(0.f, 0.f, 0.f, 0.f);
        __stcs(p + ((size_t)n << 12), s);
        float4 w0 = w[0];
        s.x = fmaf(r, s.x, w0.x);
        s.y = fmaf(r, s.y, w0.y);
        s.z = fmaf(r, s.z, w0.z);
        s.w = fmaf(r, s.w, w0.w);
        w[0] = w[1]; w[1] = w[2]; w[2] = w[3]; w[3] = wn;
    }
    ((float4*)out_state)[gid] = s;
}

__global__ __launch_bounds__(256) void scan_z_kernel(
    const float* __restrict__ ld, float* __restrict__ out_z)
{
    const int gw = (blockIdx.x * 256 + threadIdx.x) >> 5;
    const int lane = threadIdx.x & 31;
    const float r = powf(lam_from(ld), (float)C_);
    float* p = g_ks + ((size_t)(gw >> 7) * N_) * D_ + (gw & 127);

    const int n0 = lane * 4;
    float w0 = p[(n0 + 0) * D_], w1 = p[(n0 + 1) * D_];
    float w2 = p[(n0 + 2) * D_], w3 = p[(n0 + 3) * D_];
    float r2 = r * r, r4 = r2 * r2;
    float aa = r4;
    float bb = fmaf(r, fmaf(r, fmaf(r, w0, w1), w2), w3);
#pragma unroll
    for (int off = 1; off < 32; off <<= 1) {
        float ap = __shfl_up_sync(0xffffffffu, aa, off);
        float bp = __shfl_up_sync(0xffffffffu, bb, off);
        if (lane >= off) { bb = fmaf(aa, bp, bb); aa *= ap; }
    }
    float be = __shfl_up_sync(0xffffffffu, bb, 1);
    float s = (lane == 0) ? 0.f : be;
    p[(n0 + 0) * D_] = s; s = fmaf(r, s, w0);
    p[(n0 + 1) * D_] = s; s = fmaf(r, s, w1);
    p[(n0 + 2) * D_] = s; s = fmaf(r, s, w2);
    p[(n0 + 3) * D_] = s; s = fmaf(r, s, w3);
    if (lane == 31) out_z[gw] = s;
}

// ===========================================================================
// Kernel C: per-chunk output, 1024 threads (32 warps).
// S: 32 tiles of 16x8 (20 active, 5/SMSP).  Phase5: 32 tiles of 16x16.
// ===========================================================================
#define C_QR 0
#define C_KR (C_QR + 64 * S1)
#define C_VR (C_KR + 64 * S1)
#define C_ST (C_VR + 64 * S1)
#define C_AT (C_ST + 128 * S1)
#define C_PW (C_AT + 64 * SA)
#define C_RS (C_PW + 68)            // 512 (8 partial col-groups)
#define C_IV (C_RS + 512)
#define C_SZ (C_IV + 64)
#define C_FLOATS (C_SZ + 128)

__global__ __launch_bounds__(1024) void out_kernel(
    const float* __restrict__ q, const float* __restrict__ k,
    const float* __restrict__ v, const float* __restrict__ ld,
    float* __restrict__ out)
{
    extern __shared__ float sm[];
    float* QR = sm + C_QR; float* KR = sm + C_KR; float* VR = sm + C_VR;
    float* ST = sm + C_ST; float* AT = sm + C_AT;
    float* PW = sm + C_PW; float* RS = sm + C_RS; float* IV = sm + C_IV;
    float* SZ = sm + C_SZ;
    const uint32_t sb = smem_u32(sm);
    const int tid = threadIdx.x;
    const int n = blockIdx.x, b = blockIdx.y;
    const int lane = tid & 31, g = lane >> 2, t4 = lane & 3, wid = tid >> 5;

    const float lam = lam_from(ld);
    if (tid <= C_) PW[tid] = powf(lam, (float)tid);
    const size_t gbase = ((size_t)b * T_ + (size_t)n * C_) * D_;

    // phase 1: q,k,v rows -> smem; state -> ST via cp.async; z -> SZ
#pragma unroll
    for (int u = 0; u < 2; u++) {
        int e = tid + u * 1024;
        int c = e >> 5, d0 = (e & 31) * 4;
        *(float4*)&QR[c * S1 + d0] = *(const float4*)&q[gbase + (size_t)c * D_ + d0];
        *(float4*)&KR[c * S1 + d0] = *(const float4*)&k[gbase + (size_t)c * D_ + d0];
        *(float4*)&VR[c * S1 + d0] = *(const float4*)&v[gbase + (size_t)c * D_ + d0];
    }
    {
        const float* gst = g_wo + (((size_t)b * N_ + n) << 14);
#pragma unroll
        for (int u = 0; u < 4; u++) {
            int e = tid + u * 1024;
            int r = e >> 5, d0 = (e & 31) * 4;
            cp16(sb + (uint32_t)(C_ST + r * S1 + d0) * 4u, gst + (size_t)r * D_ + d0);
        }
        asm volatile("cp.async.commit_group;" ::: "memory");
    }
    if (tid < D_) SZ[tid] = g_ks[((size_t)b * N_ + n) * D_ + tid];
    __syncthreads();

    // phase 2: S = Q K^T, 32 tiles of 16x8; wids 0-19 = active (lower-tri)
    int tm, tn;
    {
        int idx = wid;
        if (idx < 20) {
            if (idx < 2)       { tm = 0; tn = idx; }
            else if (idx < 6)  { tm = 1; tn = idx - 2; }
            else if (idx < 12) { tm = 2; tn = idx - 6; }
            else               { tm = 3; tn = idx - 12; }
        } else {
            int i2 = idx - 20;
            if (i2 < 6)        { tm = 0; tn = i2 + 2; }
            else if (i2 < 10)  { tm = 1; tn = i2 - 2; }
            else               { tm = 2; tn = i2 - 4; }
        }
    }
    const bool act = (wid < 20);
    float sacc[4];
#pragma unroll
    for (int e = 0; e < 4; e++) sacc[e] = 0.f;
    if (act) {
#pragma unroll
        for (int ks = 0; ks < 16; ks++) {
            int kb = ks * 8;
            int r0 = tm * 16 + g;
            uint32_t ah[4], al[4], bh[2], bl[2];
            split2m(QR[r0 * S1 + kb + t4],           ah[0], al[0]);
            split2m(QR[(r0 + 8) * S1 + kb + t4],     ah[1], al[1]);
            split2m(QR[r0 * S1 + kb + t4 + 4],       ah[2], al[2]);
            split2m(QR[(r0 + 8) * S1 + kb + t4 + 4], ah[3], al[3]);
            int n0 = tn * 8 + g;
            split2m(KR[n0 * S1 + kb + t4],     bh[0], bl[0]);
            split2m(KR[n0 * S1 + kb + t4 + 4], bh[1], bl[1]);
            mma3(sacc, ah, al, bh, bl);
        }
    }
    __syncthreads();

    // phase 3: attn epilogue (mask/decay/partial rowsums) + dq-scale Q
    {
        int r0 = tm * 16 + g, r1 = r0 + 8;
        int cb = tn * 8 + 2 * t4;
        float v0 = (cb     <= r0) ? sacc[0] * PW[r0 - cb]     : 0.f;
        float v1 = (cb + 1 <= r0) ? sacc[1] * PW[r0 - cb - 1] : 0.f;
        float v2 = (cb     <= r1) ? sacc[2] * PW[r1 - cb]     : 0.f;
        float v3 = (cb + 1 <= r1) ? sacc[3] * PW[r1 - cb - 1] : 0.f;
        *(float2*)&AT[r0 * SA + cb] = make_float2(v0, v1);
        *(float2*)&AT[r1 * SA + cb] = make_float2(v2, v3);
        float rs0 = v0 + v1, rs1 = v2 + v3;
        rs0 += __shfl_xor_sync(0xffffffffu, rs0, 1);
        rs0 += __shfl_xor_sync(0xffffffffu, rs0, 2);
        rs1 += __shfl_xor_sync(0xffffffffu, rs1, 1);
        rs1 += __shfl_xor_sync(0xffffffffu, rs1, 2);
        if (t4 == 0) { RS[tn * 64 + r0] = rs0; RS[tn * 64 + r1] = rs1; }
    }
#pragma unroll
    for (int u = 0; u < 2; u++) {          // dq-scale Q rows (S is done)
        int e = tid + u * 1024;
        int r = e >> 5, d0 = (e & 31) * 4;
        float dq = PW[r + 1];
        float4* p = (float4*)&QR[r * S1 + d0];
        float4 x = *p;
        *p = make_float4(x.x * dq, x.y * dq, x.z * dq, x.w * dq);
    }
    asm volatile("cp.async.wait_group 0;" ::: "memory");
    __syncthreads();

    // phase 4: inv[c] = 1/max(max(rowsum,1) + (dq q).z, 1)
    if (tid < C_) {
        float cz = 0.f;
#pragma unroll 8
        for (int i = 0; i < D_; i++) cz = fmaf(QR[tid * S1 + i], SZ[i], cz);
        float iz = 0.f;
#pragma unroll
        for (int t = 0; t < 8; t++) iz += RS[t * 64 + tid];
        iz = fmaxf(iz, 1.f);
        IV[tid] = 1.f / fmaxf(iz + cz, 1.f);
    }
    __syncthreads();

    // phase 5: out = attn*V (triangular-skipped) + (dq Q)*state; 16x16 tiles
    const int wm = (wid >> 2) & 3;                       // varies within SMSP
    const int wn = (wid & 3) | ((wid >> 4) << 2);        // 0..7
    float oacc[2][4];
#pragma unroll
    for (int ni = 0; ni < 2; ni++)
#pragma unroll
        for (int e = 0; e < 4; e++) oacc[ni][e] = 0.f;

    {
        const int ks_end = 2 * wm + 2;         // attn[r][j]=0 for j > r
        for (int ks = 0; ks < ks_end; ks++) {  // intra: A=attn, B=V
            int kb = ks * 8;
            int r0 = wm * 16 + g;
            uint32_t ah[4], al[4];
            split2m(AT[r0 * SA + kb + t4],           ah[0], al[0]);
            split2m(AT[(r0 + 8) * SA + kb + t4],     ah[1], al[1]);
            split2m(AT[r0 * SA + kb + t4 + 4],       ah[2], al[2]);
            split2m(AT[(r0 + 8) * SA + kb + t4 + 4], ah[3], al[3]);
#pragma unroll
            for (int ni = 0; ni < 2; ni++) {
                int n0 = wn * 16 + ni * 8 + g;
                uint32_t bh[2], bl[2];
                split2m(VR[(kb + t4) * S1 + n0],     bh[0], bl[0]);
                split2m(VR[(kb + t4 + 4) * S1 + n0], bh[1], bl[1]);
                mma3(oacc[ni], ah, al, bh, bl);
            }
        }
    }
#pragma unroll
    for (int ks = 0; ks < 16; ks++) {          // cross: A=dq*Q, B=state
        int kb = ks * 8;
        int r0 = wm * 16 + g;
        uint32_t ah[4], al[4];
        split2m(QR[r0 * S1 + kb + t4],           ah[0], al[0]);
        split2m(QR[(r0 + 8) * S1 + kb + t4],     ah[1], al[1]);
        split2m(QR[r0 * S1 + kb + t4 + 4],       ah[2], al[2]);
        split2m(QR[(r0 + 8) * S1 + kb + t4 + 4], ah[3], al[3]);
#pragma unroll
        for (int ni = 0; ni < 2; ni++) {
            int n0 = wn * 16 + ni * 8 + g;
            uint32_t bh[2], bl[2];
            split2m(ST[(kb + t4) * S1 + n0],     bh[0], bl[0]);
            split2m(ST[(kb + t4 + 4) * S1 + n0], bh[1], bl[1]);
            mma3(oacc[ni], ah, al, bh, bl);
        }
    }

    // phase 6: normalize + store
    const float inv0 = IV[wm * 16 + g], inv1 = IV[wm * 16 + g + 8];
    float* ob = out + gbase;
#pragma unroll
    for (int ni = 0; ni < 2; ni++) {
        int cc = wn * 16 + ni * 8 + 2 * t4;
        int r0 = wm * 16 + g;
        *(float2*)&ob[(size_t)r0 * D_ + cc]       = make_float2(oacc[ni][0] * inv0, oacc[ni][1] * inv0);
        *(float2*)&ob[(size_t)(r0 + 8) * D_ + cc] = make_float2(oacc[ni][2] * inv1, oacc[ni][3] * inv1);
    }
}

// ---------------------------------------------------------------------------
extern "C" void kernel_launch(void* const* d_in, const int* in_sizes, int n_in,
                              void* d_out, int out_size)
{
    const float* q  = (const float*)d_in[0];
    const float* k  = (const float*)d_in[1];
    const float* v  = (const float*)d_in[2];
    const float* ld = (const float*)d_in[3];
    float* out = (float*)d_out;

    const int smemA = A_FLOATS * (int)sizeof(float);   // ~68 KB
    const int smemC = C_FLOATS * (int)sizeof(float);   // ~190 KB
    cudaFuncSetAttribute(wo_kernel,  cudaFuncAttributeMaxDynamicSharedMemorySize, smemA);
    cudaFuncSetAttribute(out_kernel, cudaFuncAttributeMaxDynamicSharedMemorySize, smemC);

    float* out_state = out + (size_t)B_ * T_ * D_;
    float* out_z     = out_state + (size_t)B_ * D_ * D_;

    wo_kernel<<<dim3(N_, B_), 512, smemA>>>(k, v, ld);
    scan_state_kernel<<<(B_ * D_ * D_ / 4) / 256, 256>>>(ld, out_state);
    scan_z_kernel<<<(B_ * D_ * 32) / 256, 256>>>(ld, out_z);
    out_kernel<<<dim3(N_, B_), 1024, smemC>>>(q, k, v, ld, out);
}

// round 17
// speedup vs baseline: 1.0123x; 1.0123x over previous
#include <cuda_runtime.h>
#include <cstdint>

#define B_ 16
#define T_ 8192
#define D_ 128
#define C_ 64
#define N_ 128

#define S1 132
#define SA 68

// scratch: wo / pre-chunk state ([i][j] layout), ksum / pre-chunk z
__device__ float g_wo[(size_t)B_ * N_ * D_ * D_];
__device__ float g_ks[(size_t)B_ * N_ * D_];

__device__ __forceinline__ float lam_from(const float* __restrict__ ld) {
    return 1.0f / (1.0f + __expf(-ld[0]));
}
// masked split: hi = top 19 bits (exactly tf32-representable), lo = exact residual
__device__ __forceinline__ void split2m(float x, uint32_t& h, uint32_t& l) {
    uint32_t hb = __float_as_uint(x) & 0xFFFFE000u;
    h = hb;
    l = __float_as_uint(x - __uint_as_float(hb));
}
__device__ __forceinline__ uint32_t smem_u32(const void* p) {
    uint32_t a;
    asm("{ .reg .u64 t; cvta.to.shared.u64 t, %1; cvt.u32.u64 %0, t; }" : "=r"(a) : "l"(p));
    return a;
}
__device__ __forceinline__ void cp16(uint32_t dst, const float* src) {
    asm volatile("cp.async.ca.shared.global [%0], [%1], 16;" :: "r"(dst), "l"(src) : "memory");
}
// D(16x8) += A(16x8,row) * B(8x8, B[k][n])
__device__ __forceinline__ void mma8(float* d, const uint32_t* a, const uint32_t* b) {
    asm volatile(
        "mma.sync.aligned.m16n8k8.row.col.f32.tf32.tf32.f32 "
        "{%0,%1,%2,%3},{%4,%5,%6,%7},{%8,%9},{%0,%1,%2,%3};"
        : "+f"(d[0]), "+f"(d[1]), "+f"(d[2]), "+f"(d[3])
        : "r"(a[0]), "r"(a[1]), "r"(a[2]), "r"(a[3]), "r"(b[0]), "r"(b[1]));
}
__device__ __forceinline__ void mma3(float* d, const uint32_t* ah, const uint32_t* al,
                                     const uint32_t* bh, const uint32_t* bl) {
    mma8(d, ah, bh);
    mma8(d, al, bh);
    mma8(d, ah, bl);
}

// ===========================================================================
// Kernel A: wo[i,j] = sum_c (cd_c k[c,i]) v[c,j].  (R15-proven, unchanged)
// ===========================================================================
#define A_RW 0
#define A_VV (A_RW + 64 * S1)
#define A_SC (A_VV + 64 * S1)
#define A_FLOATS (A_SC + 64)

__global__ __launch_bounds__(512) void wo_kernel(
    const float* __restrict__ k, const float* __restrict__ v,
    const float* __restrict__ ld)
{
    extern __shared__ float sm[];
    float* RW = sm + A_RW; float* VV = sm + A_VV; float* SC = sm + A_SC;
    const int tid = threadIdx.x;
    const int n = blockIdx.x, b = blockIdx.y;

    const float lam = lam_from(ld);
    if (tid < C_) SC[tid] = powf(lam, (float)(C_ - 1 - tid));
    __syncthreads();
    const size_t gbase = ((size_t)b * T_ + (size_t)n * C_) * D_;

#pragma unroll
    for (int u = 0; u < 4; u++) {
        int e = tid + u * 512;
        int c = e >> 5, d0 = (e & 31) * 4;
        float s = SC[c];
        float4 kk = *(const float4*)&k[gbase + (size_t)c * D_ + d0];
        *(float4*)&RW[c * S1 + d0] = make_float4(kk.x * s, kk.y * s, kk.z * s, kk.w * s);
        *(float4*)&VV[c * S1 + d0] = *(const float4*)&v[gbase + (size_t)c * D_ + d0];
    }
    __syncthreads();

    if (tid < D_) {
        float s = 0.f;
#pragma unroll 8
        for (int c = 0; c < C_; c++) s += RW[c * S1 + tid];
        g_ks[((size_t)b * N_ + n) * D_ + tid] = s;
    }

    const int lane = tid & 31, g = lane >> 2, t4 = lane & 3, wid = tid >> 5;
    const int wm = wid >> 2, wn = wid & 3;
    float acc[2][4][4];
#pragma unroll
    for (int mi = 0; mi < 2; mi++)
#pragma unroll
        for (int ni = 0; ni < 4; ni++)
#pragma unroll
            for (int e = 0; e < 4; e++) acc[mi][ni][e] = 0.f;

#pragma unroll
    for (int ks = 0; ks < 8; ks++) {
        int kb = ks * 8;
        uint32_t ah[2][4], al[2][4], bh[4][2], bl[4][2];
#pragma unroll
        for (int mi = 0; mi < 2; mi++) {
            int r0 = wm * 32 + mi * 16 + g;
            split2m(RW[(kb + t4) * S1 + r0],     ah[mi][0], al[mi][0]);
            split2m(RW[(kb + t4) * S1 + r0 + 8], ah[mi][1], al[mi][1]);
            split2m(RW[(kb + t4 + 4) * S1 + r0],     ah[mi][2], al[mi][2]);
            split2m(RW[(kb + t4 + 4) * S1 + r0 + 8], ah[mi][3], al[mi][3]);
        }
#pragma unroll
        for (int ni = 0; ni < 4; ni++) {
            int n0 = wn * 32 + ni * 8 + g;
            split2m(VV[(kb + t4) * S1 + n0],     bh[ni][0], bl[ni][0]);
            split2m(VV[(kb + t4 + 4) * S1 + n0], bh[ni][1], bl[ni][1]);
        }
#pragma unroll
        for (int mi = 0; mi < 2; mi++)
#pragma unroll
            for (int ni = 0; ni < 4; ni++)
                mma3(acc[mi][ni], ah[mi], al[mi], bh[ni], bl[ni]);
    }

    float* wb = g_wo + (((size_t)b * N_ + n) << 14);
#pragma unroll
    for (int mi = 0; mi < 2; mi++)
#pragma unroll
        for (int ni = 0; ni < 4; ni++) {
            int r0 = wm * 32 + mi * 16 + g, cc = wn * 32 + ni * 8 + 2 * t4;
            *(float2*)&wb[(size_t)r0 * D_ + cc]       = make_float2(acc[mi][ni][0], acc[mi][ni][1]);
            *(float2*)&wb[(size_t)(r0 + 8) * D_ + cc] = make_float2(acc[mi][ni][2], acc[mi][ni][3]);
        }
}

// ===========================================================================
// Kernel B: merged scans. blocks [0,256): state chains; [256,512): z chains.
// ===========================================================================
__global__ __launch_bounds__(256) void scan_kernel(
    const float* __restrict__ ld, float* __restrict__ out_state,
    float* __restrict__ out_z)
{
    const float r = powf(lam_from(ld), (float)C_);
    if (blockIdx.x < 256) {
        const int gid = blockIdx.x * 256 + threadIdx.x;   // [0, B*D*D/4)
        const int b = gid >> 12;
        const int e4 = gid & 4095;
        float4 s = make_float4(0.f, 0.f, 0.f, 0.f);
        float4* p = (float4*)(g_wo + (((size_t)b * N_) << 14)) + e4;
        float4 w[4];
#pragma unroll
        for (int i = 0; i < 4; i++) w[i] = __ldcs(p + ((size_t)i << 12));
#pragma unroll 4
        for (int n = 0; n < N_; n++) {
            float4 wn = (n + 4 < N_) ? __ldcs(p + ((size_t)(n + 4) << 12))
                                     : make_float4(0.f, 0.f, 0.f, 0.f);
            __stcs(p + ((size_t)n << 12), s);
            float4 w0 = w[0];
            s.x = fmaf(r, s.x, w0.x);
            s.y = fmaf(r, s.y, w0.y);
            s.z = fmaf(r, s.z, w0.z);
            s.w = fmaf(r, s.w, w0.w);
            w[0] = w[1]; w[1] = w[2]; w[2] = w[3]; w[3] = wn;
        }
        ((float4*)out_state)[gid] = s;
    } else {
        const int gw = ((blockIdx.x - 256) * 256 + threadIdx.x) >> 5;  // [0, B*D)
        const int lane = threadIdx.x & 31;
        float* p = g_ks + ((size_t)(gw >> 7) * N_) * D_ + (gw & 127);
        const int n0 = lane * 4;
        float w0 = p[(n0 + 0) * D_], w1 = p[(n0 + 1) * D_];
        float w2 = p[(n0 + 2) * D_], w3 = p[(n0 + 3) * D_];
        float r2 = r * r, r4 = r2 * r2;
        float aa = r4;
        float bb = fmaf(r, fmaf(r, fmaf(r, w0, w1), w2), w3);
#pragma unroll
        for (int off = 1; off < 32; off <<= 1) {
            float ap = __shfl_up_sync(0xffffffffu, aa, off);
            float bp = __shfl_up_sync(0xffffffffu, bb, off);
            if (lane >= off) { bb = fmaf(aa, bp, bb); aa *= ap; }
        }
        float be = __shfl_up_sync(0xffffffffu, bb, 1);
        float s = (lane == 0) ? 0.f : be;
        p[(n0 + 0) * D_] = s; s = fmaf(r, s, w0);
        p[(n0 + 1) * D_] = s; s = fmaf(r, s, w1);
        p[(n0 + 2) * D_] = s; s = fmaf(r, s, w2);
        p[(n0 + 3) * D_] = s; s = fmaf(r, s, w3);
        if (lane == 31) out_z[gw] = s;
    }
}

// ===========================================================================
// Kernel C: per-chunk output (R15 shape: 512 threads, 16x32 phase-5 tiles)
// with double-buffered fragment loads in phase 2 and phase 5 cross.
// ===========================================================================
#define C_QR 0
#define C_KR (C_QR + 64 * S1)
#define C_VR (C_KR + 64 * S1)
#define C_ST (C_VR + 64 * S1)
#define C_AT (C_ST + 128 * S1)
#define C_PW (C_AT + 64 * SA)
#define C_RS (C_PW + 68)            // 256 (4 partial col-groups)
#define C_IV (C_RS + 256)
#define C_SZ (C_IV + 64)
#define C_FLOATS (C_SZ + 128)

// tile table: wid -> (tm, tn); active (tn<=tm) balanced per SMSP: 3,3,2,2
#define TM_TAB 0x904EF9E4u
#define TN_TAB 0xE9FAD500u

__global__ __launch_bounds__(512) void out_kernel(
    const float* __restrict__ q, const float* __restrict__ k,
    const float* __restrict__ v, const float* __restrict__ ld,
    float* __restrict__ out)
{
    extern __shared__ float sm[];
    float* QR = sm + C_QR; float* KR = sm + C_KR; float* VR = sm + C_VR;
    float* ST = sm + C_ST; float* AT = sm + C_AT;
    float* PW = sm + C_PW; float* RS = sm + C_RS; float* IV = sm + C_IV;
    float* SZ = sm + C_SZ;
    const uint32_t sb = smem_u32(sm);
    const int tid = threadIdx.x;
    const int n = blockIdx.x, b = blockIdx.y;
    const int lane = tid & 31, g = lane >> 2, t4 = lane & 3, wid = tid >> 5;

    const float lam = lam_from(ld);
    if (tid <= C_) PW[tid] = powf(lam, (float)tid);
    const size_t gbase = ((size_t)b * T_ + (size_t)n * C_) * D_;

    // phase 1: q,k,v rows -> smem; state -> ST via cp.async; z -> SZ
#pragma unroll
    for (int u = 0; u < 4; u++) {
        int e = tid + u * 512;
        int c = e >> 5, d0 = (e & 31) * 4;
        *(float4*)&QR[c * S1 + d0] = *(const float4*)&q[gbase + (size_t)c * D_ + d0];
        *(float4*)&KR[c * S1 + d0] = *(const float4*)&k[gbase + (size_t)c * D_ + d0];
        *(float4*)&VR[c * S1 + d0] = *(const float4*)&v[gbase + (size_t)c * D_ + d0];
    }
    {
        const float* gst = g_wo + (((size_t)b * N_ + n) << 14);
#pragma unroll
        for (int u = 0; u < 8; u++) {
            int e = tid + u * 512;
            int r = e >> 5, d0 = (e & 31) * 4;
            cp16(sb + (uint32_t)(C_ST + r * S1 + d0) * 4u, gst + (size_t)r * D_ + d0);
        }
        asm volatile("cp.async.commit_group;" ::: "memory");
    }
    if (tid < D_) SZ[tid] = g_ks[((size_t)b * N_ + n) * D_ + tid];
    __syncthreads();

    // phase 2: S = Q K^T, triangular tile table, double-buffered fragments
    const int tm = (TM_TAB >> (2 * wid)) & 3;
    const int tn = (TN_TAB >> (2 * wid)) & 3;
    const bool act = (tn <= tm);
    float sacc[2][4];
#pragma unroll
    for (int ni = 0; ni < 2; ni++)
#pragma unroll
        for (int e = 0; e < 4; e++) sacc[ni][e] = 0.f;
    if (act) {
        uint32_t ah[2][4], al[2][4], bh[2][2][2], bl[2][2][2];
        const int r0 = tm * 16 + g;
#define LOAD_S(BUF, KS) do {                                             \
            int kb_ = (KS) * 8;                                          \
            split2m(QR[r0 * S1 + kb_ + t4],           ah[BUF][0], al[BUF][0]); \
            split2m(QR[(r0 + 8) * S1 + kb_ + t4],     ah[BUF][1], al[BUF][1]); \
            split2m(QR[r0 * S1 + kb_ + t4 + 4],       ah[BUF][2], al[BUF][2]); \
            split2m(QR[(r0 + 8) * S1 + kb_ + t4 + 4], ah[BUF][3], al[BUF][3]); \
            _Pragma("unroll")                                            \
            for (int ni_ = 0; ni_ < 2; ni_++) {                          \
                int n0_ = tn * 16 + ni_ * 8 + g;                         \
                split2m(KR[n0_ * S1 + kb_ + t4],     bh[BUF][ni_][0], bl[BUF][ni_][0]); \
                split2m(KR[n0_ * S1 + kb_ + t4 + 4], bh[BUF][ni_][1], bl[BUF][ni_][1]); \
            }                                                            \
        } while (0)
        LOAD_S(0, 0);
#pragma unroll
        for (int ks = 0; ks < 16; ks++) {
            if (ks < 15) LOAD_S((ks + 1) & 1, ks + 1);
            const int bf = ks & 1;
#pragma unroll
            for (int ni = 0; ni < 2; ni++)
                mma3(sacc[ni], ah[bf], al[bf], bh[bf][ni], bl[bf][ni]);
        }
#undef LOAD_S
    }
    __syncthreads();

    // phase 3: attn epilogue (mask/decay/partial rowsums) + dq-scale Q
    {
        int r0 = tm * 16 + g, r1 = r0 + 8;
        float rs0 = 0.f, rs1 = 0.f;
#pragma unroll
        for (int ni = 0; ni < 2; ni++) {
            int cb = tn * 16 + ni * 8 + 2 * t4;
            float v0 = (cb     <= r0) ? sacc[ni][0] * PW[r0 - cb]     : 0.f;
            float v1 = (cb + 1 <= r0) ? sacc[ni][1] * PW[r0 - cb - 1] : 0.f;
            float v2 = (cb     <= r1) ? sacc[ni][2] * PW[r1 - cb]     : 0.f;
            float v3 = (cb + 1 <= r1) ? sacc[ni][3] * PW[r1 - cb - 1] : 0.f;
            rs0 += v0 + v1; rs1 += v2 + v3;
            *(float2*)&AT[r0 * SA + cb] = make_float2(v0, v1);
            *(float2*)&AT[r1 * SA + cb] = make_float2(v2, v3);
        }
        rs0 += __shfl_xor_sync(0xffffffffu, rs0, 1);
        rs0 += __shfl_xor_sync(0xffffffffu, rs0, 2);
        rs1 += __shfl_xor_sync(0xffffffffu, rs1, 1);
        rs1 += __shfl_xor_sync(0xffffffffu, rs1, 2);
        if (t4 == 0) { RS[tn * 64 + r0] = rs0; RS[tn * 64 + r1] = rs1; }
    }
#pragma unroll
    for (int u = 0; u < 4; u++) {          // dq-scale Q rows (S is done)
        int e = tid + u * 512;
        int r = e >> 5, d0 = (e & 31) * 4;
        float dq = PW[r + 1];
        float4* p = (float4*)&QR[r * S1 + d0];
        float4 x = *p;
        *p = make_float4(x.x * dq, x.y * dq, x.z * dq, x.w * dq);
    }
    asm volatile("cp.async.wait_group 0;" ::: "memory");
    __syncthreads();

    // phase 4: inv[c] = 1/max(max(rowsum,1) + (dq q).z, 1)
    if (tid < C_) {
        float cz = 0.f;
#pragma unroll 8
        for (int i = 0; i < D_; i++) cz = fmaf(QR[tid * S1 + i], SZ[i], cz);
        float iz = fmaxf(RS[tid] + RS[64 + tid] + RS[128 + tid] + RS[192 + tid], 1.f);
        IV[tid] = 1.f / fmaxf(iz + cz, 1.f);
    }
    __syncthreads();

    // phase 5: out = attn*V (triangular-skipped) + (dq Q)*state, 16x32 tiles
    const int wm = wid >> 2, wn = wid & 3;     // wm varies within SMSP -> balanced skip
    float oacc[4][4];
#pragma unroll
    for (int ni = 0; ni < 4; ni++)
#pragma unroll
        for (int e = 0; e < 4; e++) oacc[ni][e] = 0.f;

    {
        const int ks_end = 2 * wm + 2;         // attn[r][j]=0 for j > r
        for (int ks = 0; ks < ks_end; ks++) {  // intra: A=attn, B=V
            int kb = ks * 8;
            int r0 = wm * 16 + g;
            uint32_t ah[4], al[4];
            split2m(AT[r0 * SA + kb + t4],           ah[0], al[0]);
            split2m(AT[(r0 + 8) * SA + kb + t4],     ah[1], al[1]);
            split2m(AT[r0 * SA + kb + t4 + 4],       ah[2], al[2]);
            split2m(AT[(r0 + 8) * SA + kb + t4 + 4], ah[3], al[3]);
#pragma unroll
            for (int ni = 0; ni < 4; ni++) {
                int n0 = wn * 32 + ni * 8 + g;
                uint32_t bh[2], bl[2];
                split2m(VR[(kb + t4) * S1 + n0],     bh[0], bl[0]);
                split2m(VR[(kb + t4 + 4) * S1 + n0], bh[1], bl[1]);
                mma3(oacc[ni], ah, al, bh, bl);
            }
        }
    }
    {   // cross: A=dq*Q, B=state, double-buffered
        uint32_t ah[2][4], al[2][4], bh[2][4][2], bl[2][4][2];
        const int r0 = wm * 16 + g;
#define LOAD_X(BUF, KS) do {                                             \
            int kb_ = (KS) * 8;                                          \
            split2m(QR[r0 * S1 + kb_ + t4],           ah[BUF][0], al[BUF][0]); \
            split2m(QR[(r0 + 8) * S1 + kb_ + t4],     ah[BUF][1], al[BUF][1]); \
            split2m(QR[r0 * S1 + kb_ + t4 + 4],       ah[BUF][2], al[BUF][2]); \
            split2m(QR[(r0 + 8) * S1 + kb_ + t4 + 4], ah[BUF][3], al[BUF][3]); \
            _Pragma("unroll")                                            \
            for (int ni_ = 0; ni_ < 4; ni_++) {                          \
                int n0_ = wn * 32 + ni_ * 8 + g;                         \
                split2m(ST[(kb_ + t4) * S1 + n0_],     bh[BUF][ni_][0], bl[BUF][ni_][0]); \
                split2m(ST[(kb_ + t4 + 4) * S1 + n0_], bh[BUF][ni_][1], bl[BUF][ni_][1]); \
            }                                                            \
        } while (0)
        LOAD_X(0, 0);
#pragma unroll
        for (int ks = 0; ks < 16; ks++) {
            if (ks < 15) LOAD_X((ks + 1) & 1, ks + 1);
            const int bf = ks & 1;
#pragma unroll
            for (int ni = 0; ni < 4; ni++)
                mma3(oacc[ni], ah[bf], al[bf], bh[bf][ni], bl[bf][ni]);
        }
#undef LOAD_X
    }

    // phase 6: normalize + store
    const float inv0 = IV[wm * 16 + g], inv1 = IV[wm * 16 + g + 8];
    float* ob = out + gbase;
#pragma unroll
    for (int ni = 0; ni < 4; ni++) {
        int cc = wn * 32 + ni * 8 + 2 * t4;
        int r0 = wm * 16 + g;
        *(float2*)&ob[(size_t)r0 * D_ + cc]       = make_float2(oacc[ni][0] * inv0, oacc[ni][1] * inv0);
        *(float2*)&ob[(size_t)(r0 + 8) * D_ + cc] = make_float2(oacc[ni][2] * inv1, oacc[ni][3] * inv1);
    }
}

// ---------------------------------------------------------------------------
extern "C" void kernel_launch(void* const* d_in, const int* in_sizes, int n_in,
                              void* d_out, int out_size)
{
    const float* q  = (const float*)d_in[0];
    const float* k  = (const float*)d_in[1];
    const float* v  = (const float*)d_in[2];
    const float* ld = (const float*)d_in[3];
    float* out = (float*)d_out;

    const int smemA = A_FLOATS * (int)sizeof(float);   // ~68 KB
    const int smemC = C_FLOATS * (int)sizeof(float);   // ~188 KB
    cudaFuncSetAttribute(wo_kernel,  cudaFuncAttributeMaxDynamicSharedMemorySize, smemA);
    cudaFuncSetAttribute(out_kernel, cudaFuncAttributeMaxDynamicSharedMemorySize, smemC);

    float* out_state = out + (size_t)B_ * T_ * D_;
    float* out_z     = out_state + (size_t)B_ * D_ * D_;

    wo_kernel<<<dim3(N_, B_), 512, smemA>>>(k, v, ld);
    scan_kernel<<<512, 256>>>(ld, out_state, out_z);
    out_kernel<<<dim3(N_, B_), 512, smemC>>>(q, k, v, ld, out);
}